// round 4
// baseline (speedup 1.0000x reference)
#include <cuda_runtime.h>
#include <cuda_bf16.h>
#include <stdint.h>

// Problem: B=4, L=4096, D=1024, H=16, W=64, HD=64
#define M_TOK 16384
#define D_MODEL 1024

// Static device scratch (no allocations allowed). Referenced directly from
// device code — no cudaGetSymbolAddress on the host path.
__device__ __align__(16) float g_qkv[(size_t)M_TOK * 3 * D_MODEL];  // [m, s*1024 + h*64 + hd]
__device__ __align__(16) float g_attn[(size_t)M_TOK * D_MODEL];     // attention output
__device__ __align__(16) float g_y[(size_t)M_TOK * D_MODEL];        // pre-LN residual sum

// ---------------------------------------------------------------------------
// GEMM: C[M,N] = A[M,K] @ Wt[N,K]^T + bias (+ Res), bf16x2 split on mma.sync
// Block tile 128x128, K-chunk 32, 256 threads (8 warps as 4x2 of 32x64)
// ---------------------------------------------------------------------------
#define LDSB 36

#define MMA_BF16(d, a, b)                                                      \
  asm volatile(                                                                \
      "mma.sync.aligned.m16n8k16.row.col.f32.bf16.bf16.f32 "                   \
      "{%0,%1,%2,%3},{%4,%5,%6,%7},{%8,%9},{%0,%1,%2,%3};"                     \
      : "+f"(d[0]), "+f"(d[1]), "+f"(d[2]), "+f"(d[3])                         \
      : "r"(a[0]), "r"(a[1]), "r"(a[2]), "r"(a[3]), "r"(b[0]), "r"(b[1]))

__device__ __forceinline__ void split2(float x, float y, uint32_t& hi, uint32_t& lo) {
    __nv_bfloat16 hx = __float2bfloat16(x), hy = __float2bfloat16(y);
    __nv_bfloat16 lx = __float2bfloat16(x - __bfloat162float(hx));
    __nv_bfloat16 ly = __float2bfloat16(y - __bfloat162float(hy));
    hi = (uint32_t)__bfloat16_as_ushort(hx) | ((uint32_t)__bfloat16_as_ushort(hy) << 16);
    lo = (uint32_t)__bfloat16_as_ushort(lx) | ((uint32_t)__bfloat16_as_ushort(ly) << 16);
}

template <int N, bool HAS_RES>
__device__ __forceinline__ void gemm_body(
    const float* __restrict__ A, const float* __restrict__ Wt,
    const float* __restrict__ bias, const float* __restrict__ Res,
    float* __restrict__ C) {
    const int K = 1024;
    __shared__ __align__(16) __nv_bfloat16 sAh[128][LDSB], sAl[128][LDSB];
    __shared__ __align__(16) __nv_bfloat16 sBh[128][LDSB], sBl[128][LDSB];

    const int tid = threadIdx.x;
    const int warp = tid >> 5, lane = tid & 31;
    const int wm = warp >> 1, wn = warp & 1;
    const int g = lane >> 2, t2 = lane & 3;
    const int m0 = blockIdx.y * 128, n0 = blockIdx.x * 128;

    float acc[2][8][4];
#pragma unroll
    for (int i = 0; i < 2; i++)
#pragma unroll
        for (int j = 0; j < 8; j++)
#pragma unroll
            for (int q = 0; q < 4; q++) acc[i][j][q] = 0.f;

    for (int k0 = 0; k0 < K; k0 += 32) {
#pragma unroll
        for (int it = 0; it < 4; it++) {
            int lin = tid + it * 256;           // 0..1023
            int row = lin >> 3, seg = lin & 7;  // 4 cols per seg
            float4 va = *(const float4*)(A + (size_t)(m0 + row) * K + k0 + seg * 4);
            float4 vb = *(const float4*)(Wt + (size_t)(n0 + row) * K + k0 + seg * 4);
            uint32_t h0, h1, l0, l1;
            split2(va.x, va.y, h0, l0); split2(va.z, va.w, h1, l1);
            *(uint32_t*)&sAh[row][seg * 4] = h0; *(uint32_t*)&sAh[row][seg * 4 + 2] = h1;
            *(uint32_t*)&sAl[row][seg * 4] = l0; *(uint32_t*)&sAl[row][seg * 4 + 2] = l1;
            split2(vb.x, vb.y, h0, l0); split2(vb.z, vb.w, h1, l1);
            *(uint32_t*)&sBh[row][seg * 4] = h0; *(uint32_t*)&sBh[row][seg * 4 + 2] = h1;
            *(uint32_t*)&sBl[row][seg * 4] = l0; *(uint32_t*)&sBl[row][seg * 4 + 2] = l1;
        }
        __syncthreads();

#pragma unroll
        for (int ks = 0; ks < 32; ks += 16) {
            uint32_t ah[2][4], bh[8][2];
#pragma unroll
            for (int i = 0; i < 2; i++) {
                int r = wm * 32 + i * 16 + g;
                ah[i][0] = *(const uint32_t*)&sAh[r][ks + t2 * 2];
                ah[i][1] = *(const uint32_t*)&sAh[r + 8][ks + t2 * 2];
                ah[i][2] = *(const uint32_t*)&sAh[r][ks + 8 + t2 * 2];
                ah[i][3] = *(const uint32_t*)&sAh[r + 8][ks + 8 + t2 * 2];
            }
#pragma unroll
            for (int j = 0; j < 8; j++) {
                int c = wn * 64 + j * 8 + g;
                bh[j][0] = *(const uint32_t*)&sBh[c][ks + t2 * 2];
                bh[j][1] = *(const uint32_t*)&sBh[c][ks + 8 + t2 * 2];
            }
#pragma unroll
            for (int i = 0; i < 2; i++)
#pragma unroll
                for (int j = 0; j < 8; j++) MMA_BF16(acc[i][j], ah[i], bh[j]);

            // Ah * Bl
#pragma unroll
            for (int j = 0; j < 8; j++) {
                int c = wn * 64 + j * 8 + g;
                uint32_t bl[2];
                bl[0] = *(const uint32_t*)&sBl[c][ks + t2 * 2];
                bl[1] = *(const uint32_t*)&sBl[c][ks + 8 + t2 * 2];
#pragma unroll
                for (int i = 0; i < 2; i++) MMA_BF16(acc[i][j], ah[i], bl);
            }
            // Al * Bh
#pragma unroll
            for (int i = 0; i < 2; i++) {
                int r = wm * 32 + i * 16 + g;
                uint32_t al[4];
                al[0] = *(const uint32_t*)&sAl[r][ks + t2 * 2];
                al[1] = *(const uint32_t*)&sAl[r + 8][ks + t2 * 2];
                al[2] = *(const uint32_t*)&sAl[r][ks + 8 + t2 * 2];
                al[3] = *(const uint32_t*)&sAl[r + 8][ks + 8 + t2 * 2];
#pragma unroll
                for (int j = 0; j < 8; j++) MMA_BF16(acc[i][j], al, bh[j]);
            }
        }
        __syncthreads();
    }

#pragma unroll
    for (int i = 0; i < 2; i++)
#pragma unroll
        for (int j = 0; j < 8; j++) {
            int r = m0 + wm * 32 + i * 16 + g;
            int c = n0 + wn * 64 + j * 8 + t2 * 2;
            float b0 = bias[c], b1 = bias[c + 1];
            float2 v0 = make_float2(acc[i][j][0] + b0, acc[i][j][1] + b1);
            float2 v1 = make_float2(acc[i][j][2] + b0, acc[i][j][3] + b1);
            if (HAS_RES) {
                float2 r0 = *(const float2*)(Res + (size_t)r * N + c);
                float2 r1 = *(const float2*)(Res + (size_t)(r + 8) * N + c);
                v0.x += r0.x; v0.y += r0.y; v1.x += r1.x; v1.y += r1.y;
            }
            *(float2*)(C + (size_t)r * N + c) = v0;
            *(float2*)(C + (size_t)(r + 8) * N + c) = v1;
        }
}

__global__ __launch_bounds__(256, 2) void qkv_gemm_kernel(
    const float* __restrict__ x, const float* __restrict__ Wqkv,
    const float* __restrict__ bqkv) {
    gemm_body<3072, false>(x, Wqkv, bqkv, nullptr, g_qkv);
}

__global__ __launch_bounds__(256, 2) void proj_gemm_kernel(
    const float* __restrict__ Wproj, const float* __restrict__ bproj,
    const float* __restrict__ x) {
    gemm_body<1024, true>(g_attn, Wproj, bproj, x, g_y);
}

// ---------------------------------------------------------------------------
// Windowed attention: one block per (window, head). 256 windows total.
// ---------------------------------------------------------------------------
__global__ __launch_bounds__(256) void attn_kernel() {
    __shared__ float sq[64][64];   // q; later reused as softmax probs
    __shared__ float skT[64][64];  // skT[hd][token]
    __shared__ float sv[64][64];   // sv[token][hd]
    const int gw = blockIdx.x, h = blockIdx.y;
    const int tid = threadIdx.x;
    const size_t m0 = (size_t)gw * 64;

    for (int idx = tid; idx < 64 * 16; idx += 256) {
        int row = idx >> 4, seg = idx & 15;
        const float* base = g_qkv + (m0 + row) * 3072 + h * 64 + seg * 4;
        float4 q4 = *(const float4*)(base);
        float4 k4 = *(const float4*)(base + 1024);
        float4 v4 = *(const float4*)(base + 2048);
        *(float4*)&sq[row][seg * 4] = q4;
        skT[seg * 4 + 0][row] = k4.x; skT[seg * 4 + 1][row] = k4.y;
        skT[seg * 4 + 2][row] = k4.z; skT[seg * 4 + 3][row] = k4.w;
        *(float4*)&sv[row][seg * 4] = v4;
    }
    __syncthreads();

    const int r = tid >> 2, cs = (tid & 3) * 16;
    float s[16];
#pragma unroll
    for (int j = 0; j < 16; j++) s[j] = 0.f;
#pragma unroll 4
    for (int hd = 0; hd < 64; hd++) {
        float qv = sq[r][hd];
#pragma unroll
        for (int j = 0; j < 16; j++) s[j] += qv * skT[hd][cs + j];
    }
    float mx = -1e30f;
#pragma unroll
    for (int j = 0; j < 16; j++) { s[j] *= 0.125f; mx = fmaxf(mx, s[j]); }
    mx = fmaxf(mx, __shfl_xor_sync(0xffffffffu, mx, 1));
    mx = fmaxf(mx, __shfl_xor_sync(0xffffffffu, mx, 2));
    float sum = 0.f;
#pragma unroll
    for (int j = 0; j < 16; j++) { s[j] = __expf(s[j] - mx); sum += s[j]; }
    sum += __shfl_xor_sync(0xffffffffu, sum, 1);
    sum += __shfl_xor_sync(0xffffffffu, sum, 2);
    float inv = 1.f / sum;

    __syncthreads();  // all reads of sq complete before overwrite
#pragma unroll
    for (int j = 0; j < 16; j++) sq[r][cs + j] = s[j] * inv;
    __syncthreads();

    float o[16];
#pragma unroll
    for (int j = 0; j < 16; j++) o[j] = 0.f;
#pragma unroll 4
    for (int kk = 0; kk < 64; kk++) {
        float p = sq[r][kk];
#pragma unroll
        for (int j = 0; j < 16; j++) o[j] += p * sv[kk][cs + j];
    }
    float* op = g_attn + (m0 + r) * 1024 + h * 64 + cs;
#pragma unroll
    for (int j = 0; j < 16; j += 4)
        *(float4*)(op + j) = make_float4(o[j], o[j + 1], o[j + 2], o[j + 3]);
}

// ---------------------------------------------------------------------------
// LayerNorm over last dim (1024), one block per row
// ---------------------------------------------------------------------------
__global__ __launch_bounds__(256) void ln_kernel(const float* __restrict__ gamma,
                                                 const float* __restrict__ beta,
                                                 float* __restrict__ out) {
    __shared__ float rs[8], rq[8], stats[2];
    const int row = blockIdx.x, tid = threadIdx.x;
    const float* yr = g_y + (size_t)row * 1024;
    float4 v = *(const float4*)(yr + tid * 4);
    float sm = v.x + v.y + v.z + v.w;
    float sq = v.x * v.x + v.y * v.y + v.z * v.z + v.w * v.w;
#pragma unroll
    for (int o = 16; o; o >>= 1) {
        sm += __shfl_xor_sync(0xffffffffu, sm, o);
        sq += __shfl_xor_sync(0xffffffffu, sq, o);
    }
    if ((tid & 31) == 0) { rs[tid >> 5] = sm; rq[tid >> 5] = sq; }
    __syncthreads();
    if (tid == 0) {
        float a = 0.f, b = 0.f;
#pragma unroll
        for (int i = 0; i < 8; i++) { a += rs[i]; b += rq[i]; }
        float mean = a * (1.f / 1024.f);
        float var = b * (1.f / 1024.f) - mean * mean;
        stats[0] = mean; stats[1] = rsqrtf(var + 1e-5f);
    }
    __syncthreads();
    float mean = stats[0], inv = stats[1];
    float4 g4 = *(const float4*)(gamma + tid * 4);
    float4 b4 = *(const float4*)(beta + tid * 4);
    float4 o;
    o.x = (v.x - mean) * inv * g4.x + b4.x;
    o.y = (v.y - mean) * inv * g4.y + b4.y;
    o.z = (v.z - mean) * inv * g4.z + b4.z;
    o.w = (v.w - mean) * inv * g4.w + b4.w;
    *(float4*)(out + (size_t)row * 1024 + tid * 4) = o;
}

// ---------------------------------------------------------------------------
extern "C" void kernel_launch(void* const* d_in, const int* in_sizes, int n_in,
                              void* d_out, int out_size) {
    // Identify inputs by element count (robust to metadata ordering).
    // x: 16777216, Wqkv: 3145728, bqkv: 3072, Wproj: 1048576,
    // bproj/gamma/beta: 1024 each (assigned in order of appearance).
    const float* x = nullptr; const float* Wqkv = nullptr; const float* bqkv = nullptr;
    const float* Wproj = nullptr;
    const float* v1024[3] = {nullptr, nullptr, nullptr};
    int nv = 0;
    for (int i = 0; i < n_in; i++) {
        const float* p = (const float*)d_in[i];
        switch (in_sizes[i]) {
            case 16777216: x = p; break;
            case 3145728:  Wqkv = p; break;
            case 3072:     bqkv = p; break;
            case 1048576:  Wproj = p; break;
            case 1024:     if (nv < 3) v1024[nv++] = p; break;
            default: break;
        }
    }
    const float* bproj = v1024[0];
    const float* gamma = v1024[1];
    const float* beta  = v1024[2];
    float* out = (float*)d_out;

    // 1) QKV projection: [16384,1024] x [3072,1024]^T
    qkv_gemm_kernel<<<dim3(24, 128), 256>>>(x, Wqkv, bqkv);
    // 2) Windowed attention: 256 windows x 16 heads
    attn_kernel<<<dim3(256, 16), 256>>>();
    // 3) Output projection + bias + residual
    proj_gemm_kernel<<<dim3(8, 128), 256>>>(Wproj, bproj, x);
    // 4) LayerNorm
    ln_kernel<<<M_TOK, 256>>>(gamma, beta, out);
}

// round 8
// speedup vs baseline: 1.1562x; 1.1562x over previous
#include <cuda_runtime.h>
#include <cuda_bf16.h>
#include <stdint.h>

// Problem: B=4, L=4096, D=1024, H=16, W=64, HD=64
#define M_TOK 16384
#define D_MODEL 1024
#define KDIM 1024

// Static device scratch (no allocations allowed).
__device__ __align__(16) float g_qkv[(size_t)M_TOK * 3 * D_MODEL];   // fp32 QKV
__device__ __align__(16) float g_y[(size_t)M_TOK * D_MODEL];         // pre-LN sum
// bf16 hi/lo split operands
__device__ __align__(16) __nv_bfloat16 g_xh[(size_t)M_TOK * D_MODEL];
__device__ __align__(16) __nv_bfloat16 g_xl[(size_t)M_TOK * D_MODEL];
__device__ __align__(16) __nv_bfloat16 g_wqkvh[(size_t)3 * D_MODEL * D_MODEL];
__device__ __align__(16) __nv_bfloat16 g_wqkvl[(size_t)3 * D_MODEL * D_MODEL];
__device__ __align__(16) __nv_bfloat16 g_wprojh[(size_t)D_MODEL * D_MODEL];
__device__ __align__(16) __nv_bfloat16 g_wprojl[(size_t)D_MODEL * D_MODEL];
__device__ __align__(16) __nv_bfloat16 g_ah[(size_t)M_TOK * D_MODEL];  // attn out hi
__device__ __align__(16) __nv_bfloat16 g_al[(size_t)M_TOK * D_MODEL];  // attn out lo

// ---------------------------------------------------------------------------
// helpers
// ---------------------------------------------------------------------------
#define MMA_BF16(d, a, b)                                                      \
  asm volatile(                                                                \
      "mma.sync.aligned.m16n8k16.row.col.f32.bf16.bf16.f32 "                   \
      "{%0,%1,%2,%3},{%4,%5,%6,%7},{%8,%9},{%0,%1,%2,%3};"                     \
      : "+f"(d[0]), "+f"(d[1]), "+f"(d[2]), "+f"(d[3])                         \
      : "r"(a[0]), "r"(a[1]), "r"(a[2]), "r"(a[3]), "r"(b[0]), "r"(b[1]))

__device__ __forceinline__ uint32_t smem_u32(const void* p) {
    uint32_t a;
    asm("{ .reg .u64 t; cvta.to.shared.u64 t, %1; cvt.u32.u64 %0, t; }" : "=r"(a) : "l"(p));
    return a;
}
__device__ __forceinline__ void cpa16(uint32_t dst, const void* src) {
    asm volatile("cp.async.cg.shared.global [%0], [%1], 16;" :: "r"(dst), "l"(src));
}
#define CP_COMMIT() asm volatile("cp.async.commit_group;")
#define CP_WAIT(n)  asm volatile("cp.async.wait_group %0;" :: "n"(n))

// ---------------------------------------------------------------------------
// Split conversion: fp32 -> (bf16 hi, bf16 lo), 4 elems/thread
// ---------------------------------------------------------------------------
__global__ __launch_bounds__(256) void split_kernel(const float* __restrict__ s,
                                                    __nv_bfloat16* __restrict__ h,
                                                    __nv_bfloat16* __restrict__ l) {
    size_t i = ((size_t)blockIdx.x * 256 + threadIdx.x) * 4;
    float4 v = *(const float4*)(s + i);
    __nv_bfloat16 h0 = __float2bfloat16(v.x), h1 = __float2bfloat16(v.y);
    __nv_bfloat16 h2 = __float2bfloat16(v.z), h3 = __float2bfloat16(v.w);
    __nv_bfloat16 l0 = __float2bfloat16(v.x - __bfloat162float(h0));
    __nv_bfloat16 l1 = __float2bfloat16(v.y - __bfloat162float(h1));
    __nv_bfloat16 l2 = __float2bfloat16(v.z - __bfloat162float(h2));
    __nv_bfloat16 l3 = __float2bfloat16(v.w - __bfloat162float(h3));
    uint2 hp, lp;
    hp.x = (uint32_t)__bfloat16_as_ushort(h0) | ((uint32_t)__bfloat16_as_ushort(h1) << 16);
    hp.y = (uint32_t)__bfloat16_as_ushort(h2) | ((uint32_t)__bfloat16_as_ushort(h3) << 16);
    lp.x = (uint32_t)__bfloat16_as_ushort(l0) | ((uint32_t)__bfloat16_as_ushort(l1) << 16);
    lp.y = (uint32_t)__bfloat16_as_ushort(l2) | ((uint32_t)__bfloat16_as_ushort(l3) << 16);
    *(uint2*)(h + i) = hp;
    *(uint2*)(l + i) = lp;
}

// ---------------------------------------------------------------------------
// GEMM: C[M,N] = A @ Wt^T + bias (+Res). A,Wt pre-split bf16 hi/lo.
// 128x128 tile, K-chunk 32, 2-stage cp.async double buffer, 256 threads.
// ---------------------------------------------------------------------------
#define LSTR 40                 // smem row stride in bf16 elems (80B, 16B-mult)
#define PER  (128 * LSTR)       // elems per (array, stage)
#define SMEM_BYTES (8 * PER * 2)

template <int N, bool HAS_RES>
__device__ __forceinline__ void gemm_body(
    const __nv_bfloat16* __restrict__ Agh, const __nv_bfloat16* __restrict__ Agl,
    const __nv_bfloat16* __restrict__ Bgh, const __nv_bfloat16* __restrict__ Bgl,
    const float* __restrict__ bias, const float* __restrict__ Res,
    float* __restrict__ C) {
    extern __shared__ __align__(16) __nv_bfloat16 smem[];
    __nv_bfloat16* sAh = smem;
    __nv_bfloat16* sAl = smem + 2 * PER;
    __nv_bfloat16* sBh = smem + 4 * PER;
    __nv_bfloat16* sBl = smem + 6 * PER;

    const int tid = threadIdx.x;
    const int warp = tid >> 5, lane = tid & 31;
    const int wm = warp >> 1, wn = warp & 1;
    const int g = lane >> 2, t2 = lane & 3;
    const int m0 = blockIdx.y * 128, n0 = blockIdx.x * 128;

    const uint32_t sb = smem_u32(smem);

    float acc[2][8][4];
#pragma unroll
    for (int i = 0; i < 2; i++)
#pragma unroll
        for (int j = 0; j < 8; j++)
#pragma unroll
            for (int q = 0; q < 4; q++) acc[i][j][q] = 0.f;

    // stage loader: 512 16B-chunks per array pair-half; each thread does 8 cp.async
    auto load_stage = [&](int st, int k0) {
#pragma unroll
        for (int it = 0; it < 2; it++) {
            int pos = tid + it * 256;          // 0..511
            int row = pos >> 2, ch = pos & 3;  // 4 x 16B chunks per 32-elem row
            size_t ga = (size_t)(m0 + row) * KDIM + k0 + ch * 8;
            size_t gb = (size_t)(n0 + row) * KDIM + k0 + ch * 8;
            uint32_t so = (uint32_t)(st * PER + row * LSTR + ch * 8) * 2;
            cpa16(sb + 0 * PER * 2 * 2 + so, Agh + ga);
            cpa16(sb + 2 * PER * 2 + so, Agl + ga);
            cpa16(sb + 4 * PER * 2 + so, Bgh + gb);
            cpa16(sb + 6 * PER * 2 + so, Bgl + gb);
        }
        CP_COMMIT();
    };

    const int NK = KDIM / 32;
    load_stage(0, 0);

    for (int kc = 0; kc < NK; kc++) {
        if (kc + 1 < NK) {
            load_stage((kc + 1) & 1, (kc + 1) * 32);
            CP_WAIT(1);
        } else {
            CP_WAIT(0);
        }
        __syncthreads();

        const int st = kc & 1;
        const __nv_bfloat16* pAh = sAh + st * PER;
        const __nv_bfloat16* pAl = sAl + st * PER;
        const __nv_bfloat16* pBh = sBh + st * PER;
        const __nv_bfloat16* pBl = sBl + st * PER;

#pragma unroll
        for (int ks = 0; ks < 32; ks += 16) {
            uint32_t ah[2][4], bh[8][2];
#pragma unroll
            for (int i = 0; i < 2; i++) {
                int r = wm * 32 + i * 16 + g;
                ah[i][0] = *(const uint32_t*)&pAh[r * LSTR + ks + t2 * 2];
                ah[i][1] = *(const uint32_t*)&pAh[(r + 8) * LSTR + ks + t2 * 2];
                ah[i][2] = *(const uint32_t*)&pAh[r * LSTR + ks + 8 + t2 * 2];
                ah[i][3] = *(const uint32_t*)&pAh[(r + 8) * LSTR + ks + 8 + t2 * 2];
            }
#pragma unroll
            for (int j = 0; j < 8; j++) {
                int c = wn * 64 + j * 8 + g;
                bh[j][0] = *(const uint32_t*)&pBh[c * LSTR + ks + t2 * 2];
                bh[j][1] = *(const uint32_t*)&pBh[c * LSTR + ks + 8 + t2 * 2];
            }
#pragma unroll
            for (int i = 0; i < 2; i++)
#pragma unroll
                for (int j = 0; j < 8; j++) MMA_BF16(acc[i][j], ah[i], bh[j]);

#pragma unroll
            for (int j = 0; j < 8; j++) {
                int c = wn * 64 + j * 8 + g;
                uint32_t bl[2];
                bl[0] = *(const uint32_t*)&pBl[c * LSTR + ks + t2 * 2];
                bl[1] = *(const uint32_t*)&pBl[c * LSTR + ks + 8 + t2 * 2];
#pragma unroll
                for (int i = 0; i < 2; i++) MMA_BF16(acc[i][j], ah[i], bl);
            }
#pragma unroll
            for (int i = 0; i < 2; i++) {
                int r = wm * 32 + i * 16 + g;
                uint32_t al[4];
                al[0] = *(const uint32_t*)&pAl[r * LSTR + ks + t2 * 2];
                al[1] = *(const uint32_t*)&pAl[(r + 8) * LSTR + ks + t2 * 2];
                al[2] = *(const uint32_t*)&pAl[r * LSTR + ks + 8 + t2 * 2];
                al[3] = *(const uint32_t*)&pAl[(r + 8) * LSTR + ks + 8 + t2 * 2];
#pragma unroll
                for (int j = 0; j < 8; j++) MMA_BF16(acc[i][j], al, bh[j]);
            }
        }
        __syncthreads();
    }

#pragma unroll
    for (int i = 0; i < 2; i++)
#pragma unroll
        for (int j = 0; j < 8; j++) {
            int r = m0 + wm * 32 + i * 16 + g;
            int c = n0 + wn * 64 + j * 8 + t2 * 2;
            float b0 = bias[c], b1 = bias[c + 1];
            float2 v0 = make_float2(acc[i][j][0] + b0, acc[i][j][1] + b1);
            float2 v1 = make_float2(acc[i][j][2] + b0, acc[i][j][3] + b1);
            if (HAS_RES) {
                float2 r0 = *(const float2*)(Res + (size_t)r * N + c);
                float2 r1 = *(const float2*)(Res + (size_t)(r + 8) * N + c);
                v0.x += r0.x; v0.y += r0.y; v1.x += r1.x; v1.y += r1.y;
            }
            *(float2*)(C + (size_t)r * N + c) = v0;
            *(float2*)(C + (size_t)(r + 8) * N + c) = v1;
        }
}

__global__ __launch_bounds__(256, 2) void qkv_gemm_kernel(const float* __restrict__ bqkv) {
    gemm_body<3072, false>(g_xh, g_xl, g_wqkvh, g_wqkvl, bqkv, nullptr, g_qkv);
}
__global__ __launch_bounds__(256, 2) void proj_gemm_kernel(const float* __restrict__ bproj,
                                                           const float* __restrict__ x) {
    gemm_body<1024, true>(g_ah, g_al, g_wprojh, g_wprojl, bproj, x, g_y);
}

// ---------------------------------------------------------------------------
// Windowed attention: one block per (window, head). 256 windows x 16 heads.
// Writes output pre-split as bf16 hi/lo for the proj GEMM.
// ---------------------------------------------------------------------------
__global__ __launch_bounds__(256) void attn_kernel() {
    __shared__ float sq[64][64];
    __shared__ float skT[64][64];
    __shared__ float sv[64][64];
    const int gw = blockIdx.x, h = blockIdx.y;
    const int tid = threadIdx.x;
    const size_t m0 = (size_t)gw * 64;

    for (int idx = tid; idx < 64 * 16; idx += 256) {
        int row = idx >> 4, seg = idx & 15;
        const float* base = g_qkv + (m0 + row) * 3072 + h * 64 + seg * 4;
        float4 q4 = *(const float4*)(base);
        float4 k4 = *(const float4*)(base + 1024);
        float4 v4 = *(const float4*)(base + 2048);
        *(float4*)&sq[row][seg * 4] = q4;
        skT[seg * 4 + 0][row] = k4.x; skT[seg * 4 + 1][row] = k4.y;
        skT[seg * 4 + 2][row] = k4.z; skT[seg * 4 + 3][row] = k4.w;
        *(float4*)&sv[row][seg * 4] = v4;
    }
    __syncthreads();

    const int r = tid >> 2, cs = (tid & 3) * 16;
    float s[16];
#pragma unroll
    for (int j = 0; j < 16; j++) s[j] = 0.f;
#pragma unroll 4
    for (int hd = 0; hd < 64; hd++) {
        float qv = sq[r][hd];
#pragma unroll
        for (int j = 0; j < 16; j++) s[j] += qv * skT[hd][cs + j];
    }
    float mx = -1e30f;
#pragma unroll
    for (int j = 0; j < 16; j++) { s[j] *= 0.125f; mx = fmaxf(mx, s[j]); }
    mx = fmaxf(mx, __shfl_xor_sync(0xffffffffu, mx, 1));
    mx = fmaxf(mx, __shfl_xor_sync(0xffffffffu, mx, 2));
    float sum = 0.f;
#pragma unroll
    for (int j = 0; j < 16; j++) { s[j] = __expf(s[j] - mx); sum += s[j]; }
    sum += __shfl_xor_sync(0xffffffffu, sum, 1);
    sum += __shfl_xor_sync(0xffffffffu, sum, 2);
    float inv = 1.f / sum;

    __syncthreads();
#pragma unroll
    for (int j = 0; j < 16; j++) sq[r][cs + j] = s[j] * inv;
    __syncthreads();

    float o[16];
#pragma unroll
    for (int j = 0; j < 16; j++) o[j] = 0.f;
#pragma unroll 4
    for (int kk = 0; kk < 64; kk++) {
        float p = sq[r][kk];
#pragma unroll
        for (int j = 0; j < 16; j++) o[j] += p * sv[kk][cs + j];
    }
    size_t ob = (m0 + r) * 1024 + h * 64 + cs;
    uint2 hp[2], lp[2];
#pragma unroll
    for (int q = 0; q < 2; q++) {
#pragma unroll
        for (int e = 0; e < 2; e++) {
            int j = q * 8 + e * 4;
            __nv_bfloat16 h0 = __float2bfloat16(o[j]),     h1 = __float2bfloat16(o[j + 1]);
            __nv_bfloat16 h2 = __float2bfloat16(o[j + 2]), h3 = __float2bfloat16(o[j + 3]);
            __nv_bfloat16 l0 = __float2bfloat16(o[j] - __bfloat162float(h0));
            __nv_bfloat16 l1 = __float2bfloat16(o[j + 1] - __bfloat162float(h1));
            __nv_bfloat16 l2 = __float2bfloat16(o[j + 2] - __bfloat162float(h2));
            __nv_bfloat16 l3 = __float2bfloat16(o[j + 3] - __bfloat162float(h3));
            ((uint32_t*)&hp[q])[e] =
                (uint32_t)__bfloat16_as_ushort(h0) | ((uint32_t)__bfloat16_as_ushort(h1) << 16);
            ((uint32_t*)&hp[q])[e] |= 0;  // keep simple
            ((uint32_t*)&hp[q])[e] = (uint32_t)__bfloat16_as_ushort(h0) |
                                     ((uint32_t)__bfloat16_as_ushort(h1) << 16);
            ((uint32_t*)&lp[q])[e] = (uint32_t)__bfloat16_as_ushort(l0) |
                                     ((uint32_t)__bfloat16_as_ushort(l1) << 16);
            // second pair goes in next uint32 slot via e loop; pack h2/h3 now:
            if (e == 0) {
                hp[q].x = (uint32_t)__bfloat16_as_ushort(h0) | ((uint32_t)__bfloat16_as_ushort(h1) << 16);
                lp[q].x = (uint32_t)__bfloat16_as_ushort(l0) | ((uint32_t)__bfloat16_as_ushort(l1) << 16);
            } else {
                hp[q].y = (uint32_t)__bfloat16_as_ushort(h0) | ((uint32_t)__bfloat16_as_ushort(h1) << 16);
                lp[q].y = (uint32_t)__bfloat16_as_ushort(l0) | ((uint32_t)__bfloat16_as_ushort(l1) << 16);
            }
            // h2/h3,l2/l3 belong to the *other* half of this uint2: handled by j stepping 4? No —
            // j steps 4 → only h0,h1 used per e. Write h2/h3 via separate path below.
            (void)h2; (void)h3; (void)l2; (void)l3;
        }
    }
    // Simpler, correct path: scalar-pack all 16 into 2x uint2 each (redo cleanly).
#pragma unroll
    for (int q = 0; q < 2; q++) {
        uint32_t hw[2], lw[2];
#pragma unroll
        for (int e = 0; e < 2; e++) {
            int j = q * 4 + e * 2;  // covers 0..7 over q,e with pairs
            __nv_bfloat16 h0 = __float2bfloat16(o[j]), h1 = __float2bfloat16(o[j + 1]);
            __nv_bfloat16 l0 = __float2bfloat16(o[j] - __bfloat162float(h0));
            __nv_bfloat16 l1 = __float2bfloat16(o[j + 1] - __bfloat162float(h1));
            hw[e] = (uint32_t)__bfloat16_as_ushort(h0) | ((uint32_t)__bfloat16_as_ushort(h1) << 16);
            lw[e] = (uint32_t)__bfloat16_as_ushort(l0) | ((uint32_t)__bfloat16_as_ushort(l1) << 16);
        }
        *(uint2*)(g_ah + ob + q * 4) = make_uint2(hw[0], hw[1]);
        *(uint2*)(g_al + ob + q * 4) = make_uint2(lw[0], lw[1]);
    }
#pragma unroll
    for (int q = 0; q < 2; q++) {
        uint32_t hw[2], lw[2];
#pragma unroll
        for (int e = 0; e < 2; e++) {
            int j = 8 + q * 4 + e * 2;
            __nv_bfloat16 h0 = __float2bfloat16(o[j]), h1 = __float2bfloat16(o[j + 1]);
            __nv_bfloat16 l0 = __float2bfloat16(o[j] - __bfloat162float(h0));
            __nv_bfloat16 l1 = __float2bfloat16(o[j + 1] - __bfloat162float(h1));
            hw[e] = (uint32_t)__bfloat16_as_ushort(h0) | ((uint32_t)__bfloat16_as_ushort(h1) << 16);
            lw[e] = (uint32_t)__bfloat16_as_ushort(l0) | ((uint32_t)__bfloat16_as_ushort(l1) << 16);
        }
        *(uint2*)(g_ah + ob + 8 + q * 4) = make_uint2(hw[0], hw[1]);
        *(uint2*)(g_al + ob + 8 + q * 4) = make_uint2(lw[0], lw[1]);
    }
}

// ---------------------------------------------------------------------------
// LayerNorm over last dim (1024), one block per row
// ---------------------------------------------------------------------------
__global__ __launch_bounds__(256) void ln_kernel(const float* __restrict__ gamma,
                                                 const float* __restrict__ beta,
                                                 float* __restrict__ out) {
    __shared__ float rs[8], rq[8], stats[2];
    const int row = blockIdx.x, tid = threadIdx.x;
    const float* yr = g_y + (size_t)row * 1024;
    float4 v = *(const float4*)(yr + tid * 4);
    float sm = v.x + v.y + v.z + v.w;
    float sq = v.x * v.x + v.y * v.y + v.z * v.z + v.w * v.w;
#pragma unroll
    for (int o = 16; o; o >>= 1) {
        sm += __shfl_xor_sync(0xffffffffu, sm, o);
        sq += __shfl_xor_sync(0xffffffffu, sq, o);
    }
    if ((tid & 31) == 0) { rs[tid >> 5] = sm; rq[tid >> 5] = sq; }
    __syncthreads();
    if (tid == 0) {
        float a = 0.f, b = 0.f;
#pragma unroll
        for (int i = 0; i < 8; i++) { a += rs[i]; b += rq[i]; }
        float mean = a * (1.f / 1024.f);
        float var = b * (1.f / 1024.f) - mean * mean;
        stats[0] = mean; stats[1] = rsqrtf(var + 1e-5f);
    }
    __syncthreads();
    float mean = stats[0], inv = stats[1];
    float4 g4 = *(const float4*)(gamma + tid * 4);
    float4 b4 = *(const float4*)(beta + tid * 4);
    float4 o;
    o.x = (v.x - mean) * inv * g4.x + b4.x;
    o.y = (v.y - mean) * inv * g4.y + b4.y;
    o.z = (v.z - mean) * inv * g4.z + b4.z;
    o.w = (v.w - mean) * inv * g4.w + b4.w;
    *(float4*)(out + (size_t)row * 1024 + tid * 4) = o;
}

// ---------------------------------------------------------------------------
extern "C" void kernel_launch(void* const* d_in, const int* in_sizes, int n_in,
                              void* d_out, int out_size) {
    const float* x = nullptr; const float* Wqkv = nullptr; const float* bqkv = nullptr;
    const float* Wproj = nullptr;
    const float* v1024[3] = {nullptr, nullptr, nullptr};
    int nv = 0;
    for (int i = 0; i < n_in; i++) {
        const float* p = (const float*)d_in[i];
        switch (in_sizes[i]) {
            case 16777216: x = p; break;
            case 3145728:  Wqkv = p; break;
            case 3072:     bqkv = p; break;
            case 1048576:  Wproj = p; break;
            case 1024:     if (nv < 3) v1024[nv++] = p; break;
            default: break;
        }
    }
    const float* bproj = v1024[0];
    const float* gamma = v1024[1];
    const float* beta  = v1024[2];
    float* out = (float*)d_out;

    cudaFuncSetAttribute(qkv_gemm_kernel, cudaFuncAttributeMaxDynamicSharedMemorySize, SMEM_BYTES);
    cudaFuncSetAttribute(proj_gemm_kernel, cudaFuncAttributeMaxDynamicSharedMemorySize, SMEM_BYTES);

    __nv_bfloat16 *xh, *xl, *wqh, *wql, *wph, *wpl;
    cudaGetSymbolAddress((void**)&xh, g_xh);   cudaGetSymbolAddress((void**)&xl, g_xl);
    cudaGetSymbolAddress((void**)&wqh, g_wqkvh); cudaGetSymbolAddress((void**)&wql, g_wqkvl);
    cudaGetSymbolAddress((void**)&wph, g_wprojh); cudaGetSymbolAddress((void**)&wpl, g_wprojl);

    // 0) Pre-split operands to bf16 hi/lo
    split_kernel<<<16384, 256>>>(x, xh, xl);
    split_kernel<<<3072, 256>>>(Wqkv, wqh, wql);
    split_kernel<<<1024, 256>>>(Wproj, wph, wpl);
    // 1) QKV projection
    qkv_gemm_kernel<<<dim3(24, 128), 256, SMEM_BYTES>>>(bqkv);
    // 2) Windowed attention (writes bf16 hi/lo attn output)
    attn_kernel<<<dim3(256, 16), 256>>>();
    // 3) Output projection + bias + residual
    proj_gemm_kernel<<<dim3(8, 128), 256, SMEM_BYTES>>>(bproj, x);
    // 4) LayerNorm
    ln_kernel<<<M_TOK, 256>>>(gamma, beta, out);
}